// round 11
// baseline (speedup 1.0000x reference)
#include <cuda_runtime.h>
#include <cuda_fp16.h>
#include <math.h>
#include <stdint.h>

// ---------------------------------------------------------------------------
// Problem constants
// ---------------------------------------------------------------------------
#define BATCH   4096
#define LSTM    400
#define VOCAB   73
#define NATTN   10
#define CHARLEN 64
#define NGATE   1600
#define K1PADH  512
#define K23PADH 896
#define ATTN_IN 476
#define NTILE   80
#define MTILE   64

// ---------------------------------------------------------------------------
// Scratch. X row-major half; Wt row-major [np][KPAD] half, np = unit*4+gate.
// X2/X3 cols: [0,3)=inputs, [3,403)=h(prev), [403,476)=w, [476,876)=hrec, rest 0.
// ---------------------------------------------------------------------------
__device__ __half g_Wt1[NGATE * K1PADH];
__device__ __half g_Wt2[NGATE * K23PADH];
__device__ __half g_Wt3[NGATE * K23PADH];
__device__ __half g_X1 [BATCH * K1PADH];
__device__ __half g_X2 [BATCH * K23PADH];
__device__ __half g_X3 [BATCH * K23PADH];
__device__ float  g_h1n[BATCH * LSTM];

__device__ __forceinline__ uint32_t smem_to_u32(const void* p) {
    uint32_t a;
    asm("{ .reg .u64 t; cvta.to.shared.u64 t, %1; cvt.u32.u64 %0, t; }" : "=r"(a) : "l"(p));
    return a;
}

__device__ __forceinline__ void mma_f16(float* d, const uint32_t* a, const uint32_t* b) {
    asm volatile(
        "mma.sync.aligned.m16n8k16.row.col.f32.f16.f16.f32 "
        "{%0,%1,%2,%3}, {%4,%5,%6,%7}, {%8,%9}, {%0,%1,%2,%3};"
        : "+f"(d[0]), "+f"(d[1]), "+f"(d[2]), "+f"(d[3])
        : "r"(a[0]), "r"(a[1]), "r"(a[2]), "r"(a[3]), "r"(b[0]), "r"(b[1]));
}

__device__ __forceinline__ void ldsm_x4(uint32_t& r0, uint32_t& r1, uint32_t& r2,
                                        uint32_t& r3, uint32_t addr) {
    asm volatile("ldmatrix.sync.aligned.m8n8.x4.shared.b16 {%0,%1,%2,%3}, [%4];"
                 : "=r"(r0), "=r"(r1), "=r"(r2), "=r"(r3) : "r"(addr));
}
__device__ __forceinline__ void ldsm_x2(uint32_t& r0, uint32_t& r1, uint32_t addr) {
    asm volatile("ldmatrix.sync.aligned.m8n8.x2.shared.b16 {%0,%1}, [%2];"
                 : "=r"(r0), "=r"(r1) : "r"(addr));
}

#define MBARRIER_INIT(mb, cnt) \
    asm volatile("mbarrier.init.shared.b64 [%0], %1;" \
                 :: "r"((uint32_t)(mb)), "r"((uint32_t)(cnt)) : "memory")
#define MBARRIER_EXPECT_TX(mb, bytes) \
    asm volatile("mbarrier.arrive.expect_tx.shared.b64 _, [%0], %1;" \
                 :: "r"((uint32_t)(mb)), "r"((uint32_t)(bytes)) : "memory")
#define MBARRIER_WAIT_PARITY(mb, par) do {                                   \
    uint32_t _m = (uint32_t)(mb); uint32_t _p = (uint32_t)(par); uint32_t _d;\
    asm volatile("{\n\t.reg .pred p;\n\t"                                    \
        "mbarrier.try_wait.parity.acquire.cta.shared::cta.b64 p, [%1], %2;\n\t" \
        "selp.b32 %0, 1, 0, p;\n\t}" : "=r"(_d) : "r"(_m), "r"(_p) : "memory"); \
    if (!_d) {                                                               \
        asm volatile("{\n\t.reg .pred P1;\n\t"                               \
            "WL_%=:\n\t"                                                     \
            "mbarrier.try_wait.parity.acquire.cta.shared::cta.b64 P1, [%0], %1, 0x989680;\n\t" \
            "@P1 bra.uni WD_%=;\n\t"                                         \
            "bra.uni WL_%=;\n\t"                                             \
            "WD_%=:\n\t}" :: "r"(_m), "r"(_p) : "memory");                   \
    }                                                                        \
} while (0)

#define TMA_BULK_1D(dst, src, bytes, mb) \
    asm volatile("cp.async.bulk.shared::cluster.global.mbarrier::complete_tx::bytes " \
                 "[%0], [%1], %2, [%3];" \
                 :: "r"((uint32_t)(dst)), "l"(src), "r"((uint32_t)(bytes)), \
                    "r"((uint32_t)(mb)) : "memory")

// ---------------------------------------------------------------------------
// ONE merged pack kernel: W1 | W2 | W3 | X1 | X23-static (compacted columns)
// ---------------------------------------------------------------------------
#define R_W1  (NGATE * K1PADH)
#define R_W2  (R_W1 + NGATE * K23PADH)
#define R_W3  (R_W2 + NGATE * K23PADH)
#define R_X1  (R_W3 + BATCH * K1PADH)
#define XSCOL 423
#define PACK_TOTAL (R_X1 + BATCH * XSCOL)

__global__ void pack_all(const float* __restrict__ W_ih1, const float* __restrict__ W_hh1,
                         const float* __restrict__ W_ih2, const float* __restrict__ W_hh2,
                         const float* __restrict__ W_ih3, const float* __restrict__ W_hh3,
                         const float* __restrict__ w_prev, const float* __restrict__ inputs,
                         const float* __restrict__ h1, const float* __restrict__ h2,
                         const float* __restrict__ h3,
                         __half* __restrict__ Wt1, __half* __restrict__ Wt2,
                         __half* __restrict__ Wt3, __half* __restrict__ X1,
                         __half* __restrict__ X2, __half* __restrict__ X3)
{
    int idx = blockIdx.x * blockDim.x + threadIdx.x;
    if (idx >= PACK_TOTAL) return;
    if (idx < R_W1) {
        int np = idx / K1PADH, k = idx - np * K1PADH;
        int n = (np & 3) * LSTM + (np >> 2);
        float v = 0.f;
        if (k < 76)            v = W_ih1[n * 76 + k];
        else if (k < 476)      v = W_hh1[n * LSTM + (k - 76)];
        Wt1[idx] = __float2half_rn(v);
    } else if (idx < R_W2) {
        int r = idx - R_W1;
        int np = r / K23PADH, k = r - np * K23PADH;
        int n = (np & 3) * LSTM + (np >> 2);
        float v = 0.f;
        if (k < 476)           v = W_ih2[n * 476 + k];
        else if (k < 876)      v = W_hh2[n * LSTM + (k - 476)];
        Wt2[r] = __float2half_rn(v);
    } else if (idx < R_W3) {
        int r = idx - R_W2;
        int np = r / K23PADH, k = r - np * K23PADH;
        int n = (np & 3) * LSTM + (np >> 2);
        float v = 0.f;
        if (k < 476)           v = W_ih3[n * 476 + k];
        else if (k < 876)      v = W_hh3[n * LSTM + (k - 476)];
        Wt3[r] = __float2half_rn(v);
    } else if (idx < R_X1) {
        int r = idx - R_W3;
        int b = r >> 9, c = r & 511;
        float v;
        if      (c < 73)  v = w_prev[b * 73 + c];
        else if (c < 76)  v = inputs[b * 3 + (c - 73)];
        else if (c < 476) v = h1[b * LSTM + (c - 76)];
        else              v = 0.f;
        X1[r] = __float2half_rn(v);
    } else {
        int r = idx - R_X1;
        int b = r / XSCOL, cp = r - b * XSCOL;
        int c = (cp < 3) ? cp : (cp + 473);
        __half v2, v3;
        if (c < 3) {
            __half v = __float2half_rn(inputs[b * 3 + c]);
            v2 = v; v3 = v;
        } else if (c < 876) {
            v2 = __float2half_rn(h2[b * LSTM + (c - 476)]);
            v3 = __float2half_rn(h3[b * LSTM + (c - 476)]);
        } else {
            v2 = __float2half_rn(0.f); v3 = v2;
        }
        size_t o = (size_t)b * K23PADH + c;
        X2[o] = v2; X3[o] = v3;
    }
}

// ---------------------------------------------------------------------------
// Fused fp16 mma.sync GEMM + LSTM epilogue.
// CTA 64(M) x 80(N), 4 warps (2M x 2N), warp tile 32x40, BK=64.
// Operand tiles loaded by 1D TMA bulk copies (one 128B op per tile row; 144
// rows covered by 128 threads, tid<16 issue two), completing on per-stage
// mbarriers. 2 stages, 5 CTAs/SM.
// ---------------------------------------------------------------------------
#define SMSTRH   72
#define A_BYTES  (MTILE * SMSTRH * 2)        // 9216
#define B_BYTES  (NTILE * SMSTRH * 2)        // 11520
#define STAGE_BYTES (A_BYTES + B_BYTES)      // 20736
#define TX_BYTES ((MTILE + NTILE) * 128)     // 18432 per chunk
#define SMEM_GEMM (16 + 2 * STAGE_BYTES)     // 41488

__global__ __launch_bounds__(128, 5)
void gemm_lstm(const __half* __restrict__ A, const __half* __restrict__ Bw,
               const float* __restrict__ bias, const float* __restrict__ c_in,
               float* __restrict__ h_f32, __half* __restrict__ h_h16,
               int KPAD, int NC)
{
    extern __shared__ char smem[];
    float* smemf = (float*)smem;
    const uint32_t sb = smem_to_u32(smem);
    const int tid = threadIdx.x, wid = tid >> 5, lane = tid & 31;
    const int warp_m = wid & 1, warp_n = wid >> 1;
    const int n0 = blockIdx.x * NTILE;
    const int m0 = blockIdx.y * MTILE;

    const __half* Ag = A  + (size_t)m0 * KPAD;
    const __half* Bg = Bw + (size_t)n0 * KPAD;

    const uint32_t MBAR0   = sb;             // stage 0 barrier
    const uint32_t MBAR1   = sb + 8;         // stage 1 barrier
    const uint32_t STAGE0  = sb + 16;

    float acc[2][5][4];
    #pragma unroll
    for (int mt = 0; mt < 2; mt++)
        #pragma unroll
        for (int nt = 0; nt < 5; nt++)
            #pragma unroll
            for (int q = 0; q < 4; q++) acc[mt][nt][q] = 0.f;

    // ---- ldmatrix per-thread offsets (relative to stage base) ----
    const int lane8 = lane & 7, mat = lane >> 3;
    uint32_t aoff[2], boff[2], boff2;
    #pragma unroll
    for (int mt = 0; mt < 2; mt++) {
        int arow = warp_m * 32 + mt * 16 + (mat & 1) * 8 + lane8;
        aoff[mt] = (uint32_t)((arow * SMSTRH + (mat >> 1) * 8) * 2);
    }
    #pragma unroll
    for (int p = 0; p < 2; p++) {
        int brow = warp_n * 40 + p * 16 + (mat >> 1) * 8 + lane8;
        boff[p] = (uint32_t)(A_BYTES + (brow * SMSTRH + (mat & 1) * 8) * 2);
    }
    {
        int m2 = (lane >> 3) & 1;
        int brow = warp_n * 40 + 32 + lane8;
        boff2 = (uint32_t)(A_BYTES + (brow * SMSTRH + m2 * 8) * 2);
    }

    // ---- TMA bulk issue: one 128B row copy per tile row; 144 rows over
    //      128 threads (tid<16 issue two). TX accounting must total 18432.
    auto issue_bulk = [&](int c, int stage) {
        uint32_t base = STAGE0 + stage * STAGE_BYTES;
        uint32_t mb = sb + 8 * stage;
        int k0 = c * 64;
        #pragma unroll
        for (int r = tid; r < MTILE + NTILE; r += 128) {
            uint32_t dst; const __half* src;
            if (r < MTILE) {
                dst = base + r * (SMSTRH * 2);
                src = Ag + (size_t)r * KPAD + k0;
            } else {
                int rr = r - MTILE;
                dst = base + A_BYTES + rr * (SMSTRH * 2);
                src = Bg + (size_t)rr * KPAD + k0;
            }
            TMA_BULK_1D(dst, src, 128, mb);
        }
    };

    if (tid == 0) {
        MBARRIER_INIT(MBAR0, 1);
        MBARRIER_INIT(MBAR1, 1);
        MBARRIER_EXPECT_TX(MBAR0, TX_BYTES);
    }
    __syncthreads();
    issue_bulk(0, 0);

    #pragma unroll 1
    for (int c = 0; c < NC; ++c) {
        // arm next chunk's barrier; its stage's previous phase was consumed
        // in iteration c-1, so the barrier is idle at this point.
        if (c + 1 < NC && tid == 0)
            MBARRIER_EXPECT_TX(sb + 8 * ((c + 1) & 1), TX_BYTES);
        MBARRIER_WAIT_PARITY(sb + 8 * (c & 1), (c >> 1) & 1);
        __syncthreads();   // chunk c visible to all; compute of c-1 done
                           // before its stage is overwritten below.
        if (c + 1 < NC) issue_bulk(c + 1, (c + 1) & 1);

        const uint32_t sbase = STAGE0 + (c & 1) * STAGE_BYTES;
        #pragma unroll
        for (int ks = 0; ks < 4; ks++) {
            uint32_t koff = sbase + ks * 32;
            uint32_t a[2][4], b[5][2];
            ldsm_x4(a[0][0], a[0][1], a[0][2], a[0][3], koff + aoff[0]);
            ldsm_x4(a[1][0], a[1][1], a[1][2], a[1][3], koff + aoff[1]);
            ldsm_x4(b[0][0], b[0][1], b[1][0], b[1][1], koff + boff[0]);
            ldsm_x4(b[2][0], b[2][1], b[3][0], b[3][1], koff + boff[1]);
            ldsm_x2(b[4][0], b[4][1], koff + boff2);
            #pragma unroll
            for (int mt = 0; mt < 2; mt++)
                #pragma unroll
                for (int nt = 0; nt < 5; nt++)
                    mma_f16(acc[mt][nt], a[mt], b[nt]);
        }
    }
    __syncthreads();

    // ---- epilogue: bias + LSTM cell (smem reused past barrier words) ----
    float* s_c    = smemf + 4;               // [64][21]
    float* s_h    = s_c + 64 * 21;           // [64][21]
    float* s_bias = s_h + 64 * 21;           // [80]

    const int u0g = blockIdx.x * 20;
    if (tid < NTILE) {
        int jg = n0 + tid;
        s_bias[tid] = bias[(jg & 3) * LSTM + (jg >> 2)];
    }
    #pragma unroll
    for (int i = 0; i < 3; i++) {
        int idx = i * 128 + tid;             // [0,320)
        if (idx < 320) {
            int row = idx / 5, q = idx - row * 5;
            float4 v = *(const float4*)(c_in + (size_t)(m0 + row) * LSTM + u0g + q * 4);
            s_c[row * 21 + q * 4 + 0] = v.x;
            s_c[row * 21 + q * 4 + 1] = v.y;
            s_c[row * 21 + q * 4 + 2] = v.z;
            s_c[row * 21 + q * 4 + 3] = v.w;
        }
    }
    __syncthreads();

    const int gid = lane >> 2, tig = lane & 3;
    #pragma unroll
    for (int mt = 0; mt < 2; mt++) {
        #pragma unroll
        for (int nt = 0; nt < 5; nt++) {
            float p0 = __shfl_xor_sync(0xffffffffu, acc[mt][nt][0], 1);
            float p1 = __shfl_xor_sync(0xffffffffu, acc[mt][nt][1], 1);
            float p2 = __shfl_xor_sync(0xffffffffu, acc[mt][nt][2], 1);
            float p3 = __shfl_xor_sync(0xffffffffu, acc[mt][nt][3], 1);
            if (!(lane & 1)) {
                int jb = warp_n * 40 + nt * 8 + tig * 2;
                int u  = jb >> 2;
                float bi = s_bias[jb], bf = s_bias[jb + 1];
                float bg = s_bias[jb + 2], bo = s_bias[jb + 3];
                int r0 = warp_m * 32 + mt * 16 + gid;
                #pragma unroll
                for (int hh = 0; hh < 2; hh++) {
                    int r = r0 + hh * 8;
                    float vi = (hh ? acc[mt][nt][2] : acc[mt][nt][0]) + bi;
                    float vf = (hh ? acc[mt][nt][3] : acc[mt][nt][1]) + bf;
                    float vg = (hh ? p2 : p0) + bg;
                    float vo = (hh ? p3 : p1) + bo;
                    float ii = 1.f / (1.f + expf(-vi));
                    float ff = 1.f / (1.f + expf(-vf));
                    float oo = 1.f / (1.f + expf(-vo));
                    float gg = tanhf(vg);
                    float cc = ff * s_c[r * 21 + u] + ii * gg;
                    s_h[r * 21 + u] = oo * tanhf(cc);
                }
            }
        }
    }
    __syncthreads();

    if (h_f32) {
        #pragma unroll
        for (int i = 0; i < 3; i++) {
            int idx = i * 128 + tid;
            if (idx < 320) {
                int row = idx / 5, q = idx - row * 5;
                float4 v;
                v.x = s_h[row * 21 + q * 4 + 0];
                v.y = s_h[row * 21 + q * 4 + 1];
                v.z = s_h[row * 21 + q * 4 + 2];
                v.w = s_h[row * 21 + q * 4 + 3];
                *(float4*)(h_f32 + (size_t)(m0 + row) * LSTM + u0g + q * 4) = v;
            }
        }
    }
    if (h_h16) {
        #pragma unroll
        for (int i = 0; i < 10; i++) {
            int idx = i * 128 + tid;             // [0,1280)
            int row = idx / 20, u = idx - row * 20;
            h_h16[(size_t)(m0 + row) * K23PADH + 3 + u0g + u] =
                __float2half_rn(s_h[row * 21 + u]);
        }
    }
}

// ---------------------------------------------------------------------------
// Attention: writes w as half straight into X2/X3 at column 403.
// ---------------------------------------------------------------------------
__global__ void attention_kernel(const float* __restrict__ w_prev,
                                 const float* __restrict__ inputs,
                                 const float* __restrict__ h1n,
                                 const float* __restrict__ kappa,
                                 const float* __restrict__ W_attn,
                                 const float* __restrict__ b_attn,
                                 const float* __restrict__ AV,
                                 const int* __restrict__ lens,
                                 __half* __restrict__ X2,
                                 __half* __restrict__ X3)
{
    int b = blockIdx.x;
    __shared__ float s_in[ATTN_IN];
    __shared__ float s_par[3 * NATTN];
    __shared__ float s_alpha[NATTN], s_beta[NATTN], s_kap[NATTN];
    __shared__ float s_phi[CHARLEN];
    int t = threadIdx.x;

    for (int i = t; i < 73; i += 128)  s_in[i]      = w_prev[b * 73 + i];
    if (t < 3)                          s_in[73 + t] = inputs[b * 3 + t];
    for (int i = t; i < 400; i += 128) s_in[76 + i] = h1n[b * LSTM + i];
    __syncthreads();

    {
        int out = t >> 2, ln = t & 3;
        float acc = 0.f;
        if (out < 30) {
            const float* wr = W_attn + out * ATTN_IN;
            for (int k = ln; k < ATTN_IN; k += 4) acc = fmaf(s_in[k], wr[k], acc);
        }
        acc += __shfl_down_sync(0xffffffffu, acc, 2);
        acc += __shfl_down_sync(0xffffffffu, acc, 1);
        if (ln == 0 && out < 30) {
            float x = acc + b_attn[out];
            s_par[out] = (x > 20.f) ? x : log1pf(expf(x));
        }
    }
    __syncthreads();

    if (t < NATTN) {
        s_alpha[t] = s_par[t];
        s_beta[t]  = fmaxf(s_par[NATTN + t], 0.01f);
        s_kap[t]   = kappa[b * NATTN + t] + s_par[2 * NATTN + t] * 0.04f;
    }
    __syncthreads();

    int len = lens[b];
    if (t < CHARLEN) {
        float u = (float)t;
        float phi = 0.f;
        #pragma unroll
        for (int i = 0; i < NATTN; i++) {
            float d = s_kap[i] - u;
            phi += s_alpha[i] * expf(-d * d / s_beta[i]);
        }
        s_phi[t] = (t < len) ? phi : 0.f;
    }
    __syncthreads();

    for (int v = t; v < VOCAB; v += 128) {
        float acc = 0.f;
        const float* av = AV + (size_t)b * (CHARLEN * VOCAB) + v;
        #pragma unroll 8
        for (int c = 0; c < CHARLEN; c++) acc = fmaf(s_phi[c], av[c * VOCAB], acc);
        __half hv = __float2half_rn(acc);
        X2[(size_t)b * K23PADH + 403 + v] = hv;
        X3[(size_t)b * K23PADH + 403 + v] = hv;
    }
}

// ---------------------------------------------------------------------------
// Launch
// ---------------------------------------------------------------------------
extern "C" void kernel_launch(void* const* d_in, const int* in_sizes, int n_in,
                              void* d_out, int out_size)
{
    const float* inputs = (const float*)d_in[0];
    const float* h1     = (const float*)d_in[1];
    const float* c1     = (const float*)d_in[2];
    const float* h2     = (const float*)d_in[3];
    const float* c2     = (const float*)d_in[4];
    const float* h3     = (const float*)d_in[5];
    const float* c3     = (const float*)d_in[6];
    const float* kappa  = (const float*)d_in[7];
    const float* w_prev = (const float*)d_in[8];
    const float* AV     = (const float*)d_in[9];
    const int*   lens   = (const int*)  d_in[10];
    const float* W_ih1  = (const float*)d_in[11];
    const float* W_hh1  = (const float*)d_in[12];
    const float* b1     = (const float*)d_in[13];
    const float* W_attn = (const float*)d_in[14];
    const float* b_attn = (const float*)d_in[15];
    const float* W_ih2  = (const float*)d_in[16];
    const float* W_hh2  = (const float*)d_in[17];
    const float* b2     = (const float*)d_in[18];
    const float* W_ih3  = (const float*)d_in[19];
    const float* W_hh3  = (const float*)d_in[20];
    const float* b3     = (const float*)d_in[21];
    float* out = (float*)d_out;

    __half *Wt1, *Wt2, *Wt3, *X1, *X2, *X3;
    float *h1n;
    cudaGetSymbolAddress((void**)&Wt1,  g_Wt1);
    cudaGetSymbolAddress((void**)&Wt2,  g_Wt2);
    cudaGetSymbolAddress((void**)&Wt3,  g_Wt3);
    cudaGetSymbolAddress((void**)&X1,   g_X1);
    cudaGetSymbolAddress((void**)&X2,   g_X2);
    cudaGetSymbolAddress((void**)&X3,   g_X3);
    cudaGetSymbolAddress((void**)&h1n,  g_h1n);

    cudaFuncSetAttribute(gemm_lstm, cudaFuncAttributeMaxDynamicSharedMemorySize, SMEM_GEMM);

    pack_all<<<(PACK_TOTAL + 255) / 256, 256>>>(W_ih1, W_hh1, W_ih2, W_hh2, W_ih3, W_hh3,
                                                w_prev, inputs, h1, h2, h3,
                                                Wt1, Wt2, Wt3, X1, X2, X3);

    dim3 ggrid(NGATE / NTILE, BATCH / MTILE);   // (20, 64)

    // LSTM 1: h1n fp32 (for attention) + half into X2 cols [3,403)
    gemm_lstm<<<ggrid, 128, SMEM_GEMM>>>(X1, Wt1, b1, c1, h1n, X2, K1PADH, K1PADH / 64);

    // Attention -> w half into X2/X3 cols [403,476)
    attention_kernel<<<BATCH, 128>>>(w_prev, inputs, h1n, kappa, W_attn, b_attn,
                                     AV, lens, X2, X3);

    // LSTM 2: half into X3 cols [3,403)
    gemm_lstm<<<ggrid, 128, SMEM_GEMM>>>(X2, Wt2, b2, c2, nullptr, X3, K23PADH, K23PADH / 64);

    // LSTM 3: fp32 to out
    gemm_lstm<<<ggrid, 128, SMEM_GEMM>>>(X3, Wt3, b3, c3, out, nullptr, K23PADH, K23PADH / 64);
}

// round 12
// speedup vs baseline: 1.3111x; 1.3111x over previous
#include <cuda_runtime.h>
#include <cuda_fp16.h>
#include <math.h>
#include <stdint.h>

// ---------------------------------------------------------------------------
// Problem constants
// ---------------------------------------------------------------------------
#define BATCH   4096
#define LSTM    400
#define VOCAB   73
#define NATTN   10
#define CHARLEN 64
#define NGATE   1600
#define K1PADH  512
#define K23PADH 896
#define ATTN_IN 476
#define NTILE   64              // 16 units per CTA tile
#define MTILE   64

// ---------------------------------------------------------------------------
// Scratch. X row-major half; Wt row-major [np][KPAD] half, np = unit*4+gate.
// X2/X3 cols: [0,3)=inputs, [3,403)=h(prev), [403,476)=w, [476,876)=hrec, rest 0.
// ---------------------------------------------------------------------------
__device__ __half g_Wt1[NGATE * K1PADH];
__device__ __half g_Wt2[NGATE * K23PADH];
__device__ __half g_Wt3[NGATE * K23PADH];
__device__ __half g_X1 [BATCH * K1PADH];
__device__ __half g_X2 [BATCH * K23PADH];
__device__ __half g_X3 [BATCH * K23PADH];
__device__ float  g_h1n[BATCH * LSTM];

#define CPASYNC16(dst, src) \
    asm volatile("cp.async.cg.shared.global [%0], [%1], 16;" :: "r"(dst), "l"(src) : "memory")

__device__ __forceinline__ uint32_t smem_to_u32(const void* p) {
    uint32_t a;
    asm("{ .reg .u64 t; cvta.to.shared.u64 t, %1; cvt.u32.u64 %0, t; }" : "=r"(a) : "l"(p));
    return a;
}

__device__ __forceinline__ void mma_f16(float* d, const uint32_t* a, const uint32_t* b) {
    asm volatile(
        "mma.sync.aligned.m16n8k16.row.col.f32.f16.f16.f32 "
        "{%0,%1,%2,%3}, {%4,%5,%6,%7}, {%8,%9}, {%0,%1,%2,%3};"
        : "+f"(d[0]), "+f"(d[1]), "+f"(d[2]), "+f"(d[3])
        : "r"(a[0]), "r"(a[1]), "r"(a[2]), "r"(a[3]), "r"(b[0]), "r"(b[1]));
}

__device__ __forceinline__ void ldsm_x4(uint32_t& r0, uint32_t& r1, uint32_t& r2,
                                        uint32_t& r3, uint32_t addr) {
    asm volatile("ldmatrix.sync.aligned.m8n8.x4.shared.b16 {%0,%1,%2,%3}, [%4];"
                 : "=r"(r0), "=r"(r1), "=r"(r2), "=r"(r3) : "r"(addr));
}

// ---------------------------------------------------------------------------
// ONE merged pack kernel: W1 | W2 | W3 | X1 | X23-static (compacted columns)
// ---------------------------------------------------------------------------
#define R_W1  (NGATE * K1PADH)
#define R_W2  (R_W1 + NGATE * K23PADH)
#define R_W3  (R_W2 + NGATE * K23PADH)
#define R_X1  (R_W3 + BATCH * K1PADH)
#define XSCOL 423
#define PACK_TOTAL (R_X1 + BATCH * XSCOL)

__global__ void pack_all(const float* __restrict__ W_ih1, const float* __restrict__ W_hh1,
                         const float* __restrict__ W_ih2, const float* __restrict__ W_hh2,
                         const float* __restrict__ W_ih3, const float* __restrict__ W_hh3,
                         const float* __restrict__ w_prev, const float* __restrict__ inputs,
                         const float* __restrict__ h1, const float* __restrict__ h2,
                         const float* __restrict__ h3,
                         __half* __restrict__ Wt1, __half* __restrict__ Wt2,
                         __half* __restrict__ Wt3, __half* __restrict__ X1,
                         __half* __restrict__ X2, __half* __restrict__ X3)
{
    int idx = blockIdx.x * blockDim.x + threadIdx.x;
    if (idx >= PACK_TOTAL) return;
    if (idx < R_W1) {
        int np = idx / K1PADH, k = idx - np * K1PADH;
        int n = (np & 3) * LSTM + (np >> 2);
        float v = 0.f;
        if (k < 76)            v = W_ih1[n * 76 + k];
        else if (k < 476)      v = W_hh1[n * LSTM + (k - 76)];
        Wt1[idx] = __float2half_rn(v);
    } else if (idx < R_W2) {
        int r = idx - R_W1;
        int np = r / K23PADH, k = r - np * K23PADH;
        int n = (np & 3) * LSTM + (np >> 2);
        float v = 0.f;
        if (k < 476)           v = W_ih2[n * 476 + k];
        else if (k < 876)      v = W_hh2[n * LSTM + (k - 476)];
        Wt2[r] = __float2half_rn(v);
    } else if (idx < R_W3) {
        int r = idx - R_W2;
        int np = r / K23PADH, k = r - np * K23PADH;
        int n = (np & 3) * LSTM + (np >> 2);
        float v = 0.f;
        if (k < 476)           v = W_ih3[n * 476 + k];
        else if (k < 876)      v = W_hh3[n * LSTM + (k - 476)];
        Wt3[r] = __float2half_rn(v);
    } else if (idx < R_X1) {
        int r = idx - R_W3;
        int b = r >> 9, c = r & 511;
        float v;
        if      (c < 73)  v = w_prev[b * 73 + c];
        else if (c < 76)  v = inputs[b * 3 + (c - 73)];
        else if (c < 476) v = h1[b * LSTM + (c - 76)];
        else              v = 0.f;
        X1[r] = __float2half_rn(v);
    } else {
        int r = idx - R_X1;
        int b = r / XSCOL, cp = r - b * XSCOL;
        int c = (cp < 3) ? cp : (cp + 473);
        __half v2, v3;
        if (c < 3) {
            __half v = __float2half_rn(inputs[b * 3 + c]);
            v2 = v; v3 = v;
        } else if (c < 876) {
            v2 = __float2half_rn(h2[b * LSTM + (c - 476)]);
            v3 = __float2half_rn(h3[b * LSTM + (c - 476)]);
        } else {
            v2 = __float2half_rn(0.f); v3 = v2;
        }
        size_t o = (size_t)b * K23PADH + c;
        X2[o] = v2; X3[o] = v3;
    }
}

// ---------------------------------------------------------------------------
// Fused fp16 mma.sync GEMM + LSTM epilogue.
// CTA 64(M) x 64(N), 4 warps (2M x 2N), warp tile 32x32, BK=64 halves.
// cp.async staging (r9-proven), ldmatrix fragments, 2-stage race-free
// pipeline, 6 CTAs/SM (24 warps). Grid (25,64)=1600 -> 1.80 waves over 888.
// ---------------------------------------------------------------------------
#define SMSTRH   72
#define A_BYTES  (MTILE * SMSTRH * 2)        // 9216
#define B_BYTES  (NTILE * SMSTRH * 2)        // 9216
#define STAGE_BYTES (A_BYTES + B_BYTES)      // 18432
#define SMEM_GEMM (2 * STAGE_BYTES)          // 36864

__global__ __launch_bounds__(128, 6)
void gemm_lstm(const __half* __restrict__ A, const __half* __restrict__ Bw,
               const float* __restrict__ bias, const float* __restrict__ c_in,
               float* __restrict__ h_f32, __half* __restrict__ h_h16,
               int KPAD, int NC)
{
    extern __shared__ char smem[];
    float* smemf = (float*)smem;
    const uint32_t sb = smem_to_u32(smem);
    const int tid = threadIdx.x, wid = tid >> 5, lane = tid & 31;
    const int warp_m = wid & 1, warp_n = wid >> 1;
    const int n0 = blockIdx.x * NTILE;
    const int m0 = blockIdx.y * MTILE;

    const __half* Ag = A  + (size_t)m0 * KPAD;
    const __half* Bg = Bw + (size_t)n0 * KPAD;

    float acc[2][4][4];
    #pragma unroll
    for (int mt = 0; mt < 2; mt++)
        #pragma unroll
        for (int nt = 0; nt < 4; nt++)
            #pragma unroll
            for (int q = 0; q < 4; q++) acc[mt][nt][q] = 0.f;

    // ---- ldmatrix per-thread offsets (relative to stage base) ----
    const int lane8 = lane & 7, mat = lane >> 3;
    uint32_t aoff[2], boff[2];
    #pragma unroll
    for (int mt = 0; mt < 2; mt++) {
        int arow = warp_m * 32 + mt * 16 + (mat & 1) * 8 + lane8;
        aoff[mt] = (uint32_t)((arow * SMSTRH + (mat >> 1) * 8) * 2);
    }
    #pragma unroll
    for (int p = 0; p < 2; p++) {
        int brow = warp_n * 32 + p * 16 + (mat >> 1) * 8 + lane8;
        boff[p] = (uint32_t)(A_BYTES + (brow * SMSTRH + (mat & 1) * 8) * 2);
    }

    // per chunk: A 512 x 16B ops; B 512 x 16B ops (128 threads -> 4+4 each)
    auto issue_chunk = [&](int c, int stage) {
        uint32_t abase = sb + stage * STAGE_BYTES;
        uint32_t bbase = abase + A_BYTES;
        int k0 = c * 64;
        #pragma unroll
        for (int i = 0; i < 4; i++) {
            int o = i * 128 + tid;          // [0,512)
            int row = o >> 3, seg = o & 7;
            CPASYNC16(abase + row * (SMSTRH * 2) + seg * 16,
                      Ag + (size_t)row * KPAD + k0 + seg * 8);
        }
        #pragma unroll
        for (int i = 0; i < 4; i++) {
            int o = i * 128 + tid;          // [0,512)
            int row = o >> 3, seg = o & 7;
            CPASYNC16(bbase + row * (SMSTRH * 2) + seg * 16,
                      Bg + (size_t)row * KPAD + k0 + seg * 8);
        }
        asm volatile("cp.async.commit_group;" ::: "memory");
    };

    issue_chunk(0, 0);

    #pragma unroll 1
    for (int c = 0; c < NC; ++c) {
        asm volatile("cp.async.wait_group 0;" ::: "memory");
        __syncthreads();   // chunk c visible; compute of c-1 done before overwrite
        if (c + 1 < NC) issue_chunk(c + 1, (c + 1) & 1);

        const uint32_t sbase = sb + (c & 1) * STAGE_BYTES;
        #pragma unroll
        for (int ks = 0; ks < 4; ks++) {
            uint32_t koff = sbase + ks * 32;
            uint32_t a[2][4], b[4][2];
            ldsm_x4(a[0][0], a[0][1], a[0][2], a[0][3], koff + aoff[0]);
            ldsm_x4(a[1][0], a[1][1], a[1][2], a[1][3], koff + aoff[1]);
            ldsm_x4(b[0][0], b[0][1], b[1][0], b[1][1], koff + boff[0]);
            ldsm_x4(b[2][0], b[2][1], b[3][0], b[3][1], koff + boff[1]);
            #pragma unroll
            for (int mt = 0; mt < 2; mt++)
                #pragma unroll
                for (int nt = 0; nt < 4; nt++)
                    mma_f16(acc[mt][nt], a[mt], b[nt]);
        }
    }
    __syncthreads();

    // ---- epilogue: bias + LSTM cell ----
    float* s_c    = smemf;                   // [64][17]
    float* s_h    = smemf + 64 * 17;         // [64][17]
    float* s_bias = smemf + 2 * 64 * 17;     // [64]

    const int u0g = blockIdx.x * 16;         // global unit base
    if (tid < NTILE) {
        int jg = n0 + tid;
        s_bias[tid] = bias[(jg & 3) * LSTM + (jg >> 2)];
    }
    #pragma unroll
    for (int i = 0; i < 2; i++) {
        int idx = i * 128 + tid;             // [0,256): 64 rows x 4 float4
        int row = idx >> 2, q = idx & 3;
        float4 v = *(const float4*)(c_in + (size_t)(m0 + row) * LSTM + u0g + q * 4);
        s_c[row * 17 + q * 4 + 0] = v.x;
        s_c[row * 17 + q * 4 + 1] = v.y;
        s_c[row * 17 + q * 4 + 2] = v.z;
        s_c[row * 17 + q * 4 + 3] = v.w;
    }
    __syncthreads();

    const int gid = lane >> 2, tig = lane & 3;
    #pragma unroll
    for (int mt = 0; mt < 2; mt++) {
        #pragma unroll
        for (int nt = 0; nt < 4; nt++) {
            float p0 = __shfl_xor_sync(0xffffffffu, acc[mt][nt][0], 1);
            float p1 = __shfl_xor_sync(0xffffffffu, acc[mt][nt][1], 1);
            float p2 = __shfl_xor_sync(0xffffffffu, acc[mt][nt][2], 1);
            float p3 = __shfl_xor_sync(0xffffffffu, acc[mt][nt][3], 1);
            if (!(lane & 1)) {
                int jb = warp_n * 32 + nt * 8 + tig * 2;   // packed col (gate i)
                int u  = jb >> 2;                           // unit within CTA
                float bi = s_bias[jb], bf = s_bias[jb + 1];
                float bg = s_bias[jb + 2], bo = s_bias[jb + 3];
                int r0 = warp_m * 32 + mt * 16 + gid;
                #pragma unroll
                for (int hh = 0; hh < 2; hh++) {
                    int r = r0 + hh * 8;
                    float vi = (hh ? acc[mt][nt][2] : acc[mt][nt][0]) + bi;
                    float vf = (hh ? acc[mt][nt][3] : acc[mt][nt][1]) + bf;
                    float vg = (hh ? p2 : p0) + bg;
                    float vo = (hh ? p3 : p1) + bo;
                    float ii = 1.f / (1.f + expf(-vi));
                    float ff = 1.f / (1.f + expf(-vf));
                    float oo = 1.f / (1.f + expf(-vo));
                    float gg = tanhf(vg);
                    float cc = ff * s_c[r * 17 + u] + ii * gg;
                    s_h[r * 17 + u] = oo * tanhf(cc);
                }
            }
        }
    }
    __syncthreads();

    if (h_f32) {
        #pragma unroll
        for (int i = 0; i < 2; i++) {
            int idx = i * 128 + tid;
            int row = idx >> 2, q = idx & 3;
            float4 v;
            v.x = s_h[row * 17 + q * 4 + 0];
            v.y = s_h[row * 17 + q * 4 + 1];
            v.z = s_h[row * 17 + q * 4 + 2];
            v.w = s_h[row * 17 + q * 4 + 3];
            *(float4*)(h_f32 + (size_t)(m0 + row) * LSTM + u0g + q * 4) = v;
        }
    }
    if (h_h16) {
        #pragma unroll
        for (int i = 0; i < 8; i++) {
            int idx = i * 128 + tid;             // [0,1024): 64 rows x 16 units
            int row = idx >> 4, u = idx & 15;
            h_h16[(size_t)(m0 + row) * K23PADH + 3 + u0g + u] =
                __float2half_rn(s_h[row * 17 + u]);
        }
    }
}

// ---------------------------------------------------------------------------
// Attention: writes w as half straight into X2/X3 at column 403.
// ---------------------------------------------------------------------------
__global__ void attention_kernel(const float* __restrict__ w_prev,
                                 const float* __restrict__ inputs,
                                 const float* __restrict__ h1n,
                                 const float* __restrict__ kappa,
                                 const float* __restrict__ W_attn,
                                 const float* __restrict__ b_attn,
                                 const float* __restrict__ AV,
                                 const int* __restrict__ lens,
                                 __half* __restrict__ X2,
                                 __half* __restrict__ X3)
{
    int b = blockIdx.x;
    __shared__ float s_in[ATTN_IN];
    __shared__ float s_par[3 * NATTN];
    __shared__ float s_alpha[NATTN], s_beta[NATTN], s_kap[NATTN];
    __shared__ float s_phi[CHARLEN];
    int t = threadIdx.x;

    for (int i = t; i < 73; i += 128)  s_in[i]      = w_prev[b * 73 + i];
    if (t < 3)                          s_in[73 + t] = inputs[b * 3 + t];
    for (int i = t; i < 400; i += 128) s_in[76 + i] = h1n[b * LSTM + i];
    __syncthreads();

    {
        int out = t >> 2, ln = t & 3;
        float acc = 0.f;
        if (out < 30) {
            const float* wr = W_attn + out * ATTN_IN;
            for (int k = ln; k < ATTN_IN; k += 4) acc = fmaf(s_in[k], wr[k], acc);
        }
        acc += __shfl_down_sync(0xffffffffu, acc, 2);
        acc += __shfl_down_sync(0xffffffffu, acc, 1);
        if (ln == 0 && out < 30) {
            float x = acc + b_attn[out];
            s_par[out] = (x > 20.f) ? x : log1pf(expf(x));
        }
    }
    __syncthreads();

    if (t < NATTN) {
        s_alpha[t] = s_par[t];
        s_beta[t]  = fmaxf(s_par[NATTN + t], 0.01f);
        s_kap[t]   = kappa[b * NATTN + t] + s_par[2 * NATTN + t] * 0.04f;
    }
    __syncthreads();

    int len = lens[b];
    if (t < CHARLEN) {
        float u = (float)t;
        float phi = 0.f;
        #pragma unroll
        for (int i = 0; i < NATTN; i++) {
            float d = s_kap[i] - u;
            phi += s_alpha[i] * expf(-d * d / s_beta[i]);
        }
        s_phi[t] = (t < len) ? phi : 0.f;
    }
    __syncthreads();

    for (int v = t; v < VOCAB; v += 128) {
        float acc = 0.f;
        const float* av = AV + (size_t)b * (CHARLEN * VOCAB) + v;
        #pragma unroll 8
        for (int c = 0; c < CHARLEN; c++) acc = fmaf(s_phi[c], av[c * VOCAB], acc);
        __half hv = __float2half_rn(acc);
        X2[(size_t)b * K23PADH + 403 + v] = hv;
        X3[(size_t)b * K23PADH + 403 + v] = hv;
    }
}

// ---------------------------------------------------------------------------
// Launch
// ---------------------------------------------------------------------------
extern "C" void kernel_launch(void* const* d_in, const int* in_sizes, int n_in,
                              void* d_out, int out_size)
{
    const float* inputs = (const float*)d_in[0];
    const float* h1     = (const float*)d_in[1];
    const float* c1     = (const float*)d_in[2];
    const float* h2     = (const float*)d_in[3];
    const float* c2     = (const float*)d_in[4];
    const float* h3     = (const float*)d_in[5];
    const float* c3     = (const float*)d_in[6];
    const float* kappa  = (const float*)d_in[7];
    const float* w_prev = (const float*)d_in[8];
    const float* AV     = (const float*)d_in[9];
    const int*   lens   = (const int*)  d_in[10];
    const float* W_ih1  = (const float*)d_in[11];
    const float* W_hh1  = (const float*)d_in[12];
    const float* b1     = (const float*)d_in[13];
    const float* W_attn = (const float*)d_in[14];
    const float* b_attn = (const float*)d_in[15];
    const float* W_ih2  = (const float*)d_in[16];
    const float* W_hh2  = (const float*)d_in[17];
    const float* b2     = (const float*)d_in[18];
    const float* W_ih3  = (const float*)d_in[19];
    const float* W_hh3  = (const float*)d_in[20];
    const float* b3     = (const float*)d_in[21];
    float* out = (float*)d_out;

    __half *Wt1, *Wt2, *Wt3, *X1, *X2, *X3;
    float *h1n;
    cudaGetSymbolAddress((void**)&Wt1,  g_Wt1);
    cudaGetSymbolAddress((void**)&Wt2,  g_Wt2);
    cudaGetSymbolAddress((void**)&Wt3,  g_Wt3);
    cudaGetSymbolAddress((void**)&X1,   g_X1);
    cudaGetSymbolAddress((void**)&X2,   g_X2);
    cudaGetSymbolAddress((void**)&X3,   g_X3);
    cudaGetSymbolAddress((void**)&h1n,  g_h1n);

    cudaFuncSetAttribute(gemm_lstm, cudaFuncAttributeMaxDynamicSharedMemorySize, SMEM_GEMM);

    pack_all<<<(PACK_TOTAL + 255) / 256, 256>>>(W_ih1, W_hh1, W_ih2, W_hh2, W_ih3, W_hh3,
                                                w_prev, inputs, h1, h2, h3,
                                                Wt1, Wt2, Wt3, X1, X2, X3);

    dim3 ggrid(NGATE / NTILE, BATCH / MTILE);   // (25, 64)

    // LSTM 1: h1n fp32 (for attention) + half into X2 cols [3,403)
    gemm_lstm<<<ggrid, 128, SMEM_GEMM>>>(X1, Wt1, b1, c1, h1n, X2, K1PADH, K1PADH / 64);

    // Attention -> w half into X2/X3 cols [403,476)
    attention_kernel<<<BATCH, 128>>>(w_prev, inputs, h1n, kappa, W_attn, b_attn,
                                     AV, lens, X2, X3);

    // LSTM 2: half into X3 cols [3,403)
    gemm_lstm<<<ggrid, 128, SMEM_GEMM>>>(X2, Wt2, b2, c2, nullptr, X3, K23PADH, K23PADH / 64);

    // LSTM 3: fp32 to out
    gemm_lstm<<<ggrid, 128, SMEM_GEMM>>>(X3, Wt3, b3, c3, out, nullptr, K23PADH, K23PADH / 64);
}

// round 13
// speedup vs baseline: 1.3269x; 1.0120x over previous
#include <cuda_runtime.h>
#include <cuda_fp16.h>
#include <math.h>
#include <stdint.h>

// ---------------------------------------------------------------------------
// Problem constants
// ---------------------------------------------------------------------------
#define BATCH   4096
#define LSTM    400
#define VOCAB   73
#define NATTN   10
#define CHARLEN 64
#define NGATE   1600
#define K1PADH  512
#define K23PADH 896
#define ATTN_IN 476
#define NTILE   64              // 16 units per CTA tile
#define MTILE   64

// ---------------------------------------------------------------------------
// Scratch. X row-major half; Wt row-major [np][KPAD] half, np = unit*4+gate.
// X2/X3 cols: [0,3)=inputs, [3,403)=h(prev), [403,476)=w, [476,876)=hrec, rest 0.
// ---------------------------------------------------------------------------
__device__ __half g_Wt1[NGATE * K1PADH];
__device__ __half g_Wt2[NGATE * K23PADH];
__device__ __half g_Wt3[NGATE * K23PADH];
__device__ __half g_X1 [BATCH * K1PADH];
__device__ __half g_X2 [BATCH * K23PADH];
__device__ __half g_X3 [BATCH * K23PADH];
__device__ float  g_h1n[BATCH * LSTM];

#define CPASYNC16(dst, src) \
    asm volatile("cp.async.cg.shared.global [%0], [%1], 16;" :: "r"(dst), "l"(src) : "memory")

__device__ __forceinline__ uint32_t smem_to_u32(const void* p) {
    uint32_t a;
    asm("{ .reg .u64 t; cvta.to.shared.u64 t, %1; cvt.u32.u64 %0, t; }" : "=r"(a) : "l"(p));
    return a;
}

// SW128 swizzle: conflict-free for 16B-granular row accesses within 1KB atoms.
__device__ __forceinline__ uint32_t swz(uint32_t off) {
    return off ^ ((off >> 3) & 0x70);
}

__device__ __forceinline__ void mma_f16(float* d, const uint32_t* a, const uint32_t* b) {
    asm volatile(
        "mma.sync.aligned.m16n8k16.row.col.f32.f16.f16.f32 "
        "{%0,%1,%2,%3}, {%4,%5,%6,%7}, {%8,%9}, {%0,%1,%2,%3};"
        : "+f"(d[0]), "+f"(d[1]), "+f"(d[2]), "+f"(d[3])
        : "r"(a[0]), "r"(a[1]), "r"(a[2]), "r"(a[3]), "r"(b[0]), "r"(b[1]));
}

__device__ __forceinline__ void ldsm_x4(uint32_t& r0, uint32_t& r1, uint32_t& r2,
                                        uint32_t& r3, uint32_t addr) {
    asm volatile("ldmatrix.sync.aligned.m8n8.x4.shared.b16 {%0,%1,%2,%3}, [%4];"
                 : "=r"(r0), "=r"(r1), "=r"(r2), "=r"(r3) : "r"(addr));
}

// ---------------------------------------------------------------------------
// ONE merged pack kernel: W1 | W2 | W3 | X1 | X23-static (compacted columns)
// ---------------------------------------------------------------------------
#define R_W1  (NGATE * K1PADH)
#define R_W2  (R_W1 + NGATE * K23PADH)
#define R_W3  (R_W2 + NGATE * K23PADH)
#define R_X1  (R_W3 + BATCH * K1PADH)
#define XSCOL 423
#define PACK_TOTAL (R_X1 + BATCH * XSCOL)

__global__ void pack_all(const float* __restrict__ W_ih1, const float* __restrict__ W_hh1,
                         const float* __restrict__ W_ih2, const float* __restrict__ W_hh2,
                         const float* __restrict__ W_ih3, const float* __restrict__ W_hh3,
                         const float* __restrict__ w_prev, const float* __restrict__ inputs,
                         const float* __restrict__ h1, const float* __restrict__ h2,
                         const float* __restrict__ h3,
                         __half* __restrict__ Wt1, __half* __restrict__ Wt2,
                         __half* __restrict__ Wt3, __half* __restrict__ X1,
                         __half* __restrict__ X2, __half* __restrict__ X3)
{
    int idx = blockIdx.x * blockDim.x + threadIdx.x;
    if (idx >= PACK_TOTAL) return;
    if (idx < R_W1) {
        int np = idx / K1PADH, k = idx - np * K1PADH;
        int n = (np & 3) * LSTM + (np >> 2);
        float v = 0.f;
        if (k < 76)            v = W_ih1[n * 76 + k];
        else if (k < 476)      v = W_hh1[n * LSTM + (k - 76)];
        Wt1[idx] = __float2half_rn(v);
    } else if (idx < R_W2) {
        int r = idx - R_W1;
        int np = r / K23PADH, k = r - np * K23PADH;
        int n = (np & 3) * LSTM + (np >> 2);
        float v = 0.f;
        if (k < 476)           v = W_ih2[n * 476 + k];
        else if (k < 876)      v = W_hh2[n * LSTM + (k - 476)];
        Wt2[r] = __float2half_rn(v);
    } else if (idx < R_W3) {
        int r = idx - R_W2;
        int np = r / K23PADH, k = r - np * K23PADH;
        int n = (np & 3) * LSTM + (np >> 2);
        float v = 0.f;
        if (k < 476)           v = W_ih3[n * 476 + k];
        else if (k < 876)      v = W_hh3[n * LSTM + (k - 476)];
        Wt3[r] = __float2half_rn(v);
    } else if (idx < R_X1) {
        int r = idx - R_W3;
        int b = r >> 9, c = r & 511;
        float v;
        if      (c < 73)  v = w_prev[b * 73 + c];
        else if (c < 76)  v = inputs[b * 3 + (c - 73)];
        else if (c < 476) v = h1[b * LSTM + (c - 76)];
        else              v = 0.f;
        X1[r] = __float2half_rn(v);
    } else {
        int r = idx - R_X1;
        int b = r / XSCOL, cp = r - b * XSCOL;
        int c = (cp < 3) ? cp : (cp + 473);
        __half v2, v3;
        if (c < 3) {
            __half v = __float2half_rn(inputs[b * 3 + c]);
            v2 = v; v3 = v;
        } else if (c < 876) {
            v2 = __float2half_rn(h2[b * LSTM + (c - 476)]);
            v3 = __float2half_rn(h3[b * LSTM + (c - 476)]);
        } else {
            v2 = __float2half_rn(0.f); v3 = v2;
        }
        size_t o = (size_t)b * K23PADH + c;
        X2[o] = v2; X3[o] = v3;
    }
}

// ---------------------------------------------------------------------------
// Fused fp16 mma.sync GEMM + LSTM epilogue.
// CTA 64(M) x 64(N), 4 warps (2M x 2N), warp tile 32x32, BK=64 halves.
// SW128-swizzled smem (128B rows, no padding): stage = 16KB, 2 stages = 32KB
// -> 7 CTAs/SM (28 warps). cp.async staging + ldmatrix fragments, race-free
// 2-stage pipeline. Grid (25,64)=1600 over 1036 slots = 1.54 waves.
// ---------------------------------------------------------------------------
#define A_BYTES  (MTILE * 128)               // 8192
#define B_BYTES  (NTILE * 128)               // 8192
#define STAGE_BYTES (A_BYTES + B_BYTES)      // 16384
#define SMEM_GEMM (2 * STAGE_BYTES)          // 32768

__global__ __launch_bounds__(128, 7)
void gemm_lstm(const __half* __restrict__ A, const __half* __restrict__ Bw,
               const float* __restrict__ bias, const float* __restrict__ c_in,
               float* __restrict__ h_f32, __half* __restrict__ h_h16,
               int KPAD, int NC)
{
    extern __shared__ char smem[];
    float* smemf = (float*)smem;
    const uint32_t sb = smem_to_u32(smem);
    const int tid = threadIdx.x, wid = tid >> 5, lane = tid & 31;
    const int warp_m = wid & 1, warp_n = wid >> 1;
    const int n0 = blockIdx.x * NTILE;
    const int m0 = blockIdx.y * MTILE;

    const __half* Ag = A  + (size_t)m0 * KPAD;
    const __half* Bg = Bw + (size_t)n0 * KPAD;

    float acc[2][4][4];
    #pragma unroll
    for (int mt = 0; mt < 2; mt++)
        #pragma unroll
        for (int nt = 0; nt < 4; nt++)
            #pragma unroll
            for (int q = 0; q < 4; q++) acc[mt][nt][q] = 0.f;

    // ---- ldmatrix logical per-lane row offsets (pre-swizzle) ----
    const int lane8 = lane & 7, mat = lane >> 3;
    uint32_t abase[2], bbase[2];
    #pragma unroll
    for (int mt = 0; mt < 2; mt++) {
        int arow = warp_m * 32 + mt * 16 + (mat & 1) * 8 + lane8;
        abase[mt] = (uint32_t)(arow * 128 + (mat >> 1) * 16);
    }
    #pragma unroll
    for (int p = 0; p < 2; p++) {
        int brow = warp_n * 32 + p * 16 + (mat >> 1) * 8 + lane8;
        bbase[p] = (uint32_t)(brow * 128 + (mat & 1) * 16);
    }

    // per chunk: A 512 x 16B ops; B 512 x 16B ops (128 threads -> 4+4 each)
    auto issue_chunk = [&](int c, int stage) {
        uint32_t abuf = sb + stage * STAGE_BYTES;
        uint32_t bbuf = abuf + A_BYTES;
        int k0 = c * 64;
        #pragma unroll
        for (int i = 0; i < 4; i++) {
            int o = i * 128 + tid;          // [0,512)
            int row = o >> 3, seg = o & 7;
            CPASYNC16(abuf + swz(row * 128 + seg * 16),
                      Ag + (size_t)row * KPAD + k0 + seg * 8);
        }
        #pragma unroll
        for (int i = 0; i < 4; i++) {
            int o = i * 128 + tid;          // [0,512)
            int row = o >> 3, seg = o & 7;
            CPASYNC16(bbuf + swz(row * 128 + seg * 16),
                      Bg + (size_t)row * KPAD + k0 + seg * 8);
        }
        asm volatile("cp.async.commit_group;" ::: "memory");
    };

    issue_chunk(0, 0);

    #pragma unroll 1
    for (int c = 0; c < NC; ++c) {
        asm volatile("cp.async.wait_group 0;" ::: "memory");
        __syncthreads();   // chunk c visible; compute of c-1 done before overwrite
        if (c + 1 < NC) issue_chunk(c + 1, (c + 1) & 1);

        const uint32_t abuf = sb + (c & 1) * STAGE_BYTES;
        const uint32_t bbuf = abuf + A_BYTES;
        #pragma unroll
        for (int ks = 0; ks < 4; ks++) {
            uint32_t kb = ks * 32;          // 16 halves per k-step
            uint32_t a[2][4], b[4][2];
            ldsm_x4(a[0][0], a[0][1], a[0][2], a[0][3], abuf + swz(abase[0] + kb));
            ldsm_x4(a[1][0], a[1][1], a[1][2], a[1][3], abuf + swz(abase[1] + kb));
            ldsm_x4(b[0][0], b[0][1], b[1][0], b[1][1], bbuf + swz(bbase[0] + kb));
            ldsm_x4(b[2][0], b[2][1], b[3][0], b[3][1], bbuf + swz(bbase[1] + kb));
            #pragma unroll
            for (int mt = 0; mt < 2; mt++)
                #pragma unroll
                for (int nt = 0; nt < 4; nt++)
                    mma_f16(acc[mt][nt], a[mt], b[nt]);
        }
    }
    __syncthreads();

    // ---- epilogue: bias + LSTM cell ----
    float* s_c    = smemf;                   // [64][17]
    float* s_h    = smemf + 64 * 17;         // [64][17]
    float* s_bias = smemf + 2 * 64 * 17;     // [64]

    const int u0g = blockIdx.x * 16;         // global unit base
    if (tid < NTILE) {
        int jg = n0 + tid;
        s_bias[tid] = bias[(jg & 3) * LSTM + (jg >> 2)];
    }
    #pragma unroll
    for (int i = 0; i < 2; i++) {
        int idx = i * 128 + tid;             // [0,256): 64 rows x 4 float4
        int row = idx >> 2, q = idx & 3;
        float4 v = *(const float4*)(c_in + (size_t)(m0 + row) * LSTM + u0g + q * 4);
        s_c[row * 17 + q * 4 + 0] = v.x;
        s_c[row * 17 + q * 4 + 1] = v.y;
        s_c[row * 17 + q * 4 + 2] = v.z;
        s_c[row * 17 + q * 4 + 3] = v.w;
    }
    __syncthreads();

    const int gid = lane >> 2, tig = lane & 3;
    #pragma unroll
    for (int mt = 0; mt < 2; mt++) {
        #pragma unroll
        for (int nt = 0; nt < 4; nt++) {
            float p0 = __shfl_xor_sync(0xffffffffu, acc[mt][nt][0], 1);
            float p1 = __shfl_xor_sync(0xffffffffu, acc[mt][nt][1], 1);
            float p2 = __shfl_xor_sync(0xffffffffu, acc[mt][nt][2], 1);
            float p3 = __shfl_xor_sync(0xffffffffu, acc[mt][nt][3], 1);
            if (!(lane & 1)) {
                int jb = warp_n * 32 + nt * 8 + tig * 2;   // packed col (gate i)
                int u  = jb >> 2;                           // unit within CTA
                float bi = s_bias[jb], bf = s_bias[jb + 1];
                float bg = s_bias[jb + 2], bo = s_bias[jb + 3];
                int r0 = warp_m * 32 + mt * 16 + gid;
                #pragma unroll
                for (int hh = 0; hh < 2; hh++) {
                    int r = r0 + hh * 8;
                    float vi = (hh ? acc[mt][nt][2] : acc[mt][nt][0]) + bi;
                    float vf = (hh ? acc[mt][nt][3] : acc[mt][nt][1]) + bf;
                    float vg = (hh ? p2 : p0) + bg;
                    float vo = (hh ? p3 : p1) + bo;
                    float ii = 1.f / (1.f + expf(-vi));
                    float ff = 1.f / (1.f + expf(-vf));
                    float oo = 1.f / (1.f + expf(-vo));
                    float gg = tanhf(vg);
                    float cc = ff * s_c[r * 17 + u] + ii * gg;
                    s_h[r * 17 + u] = oo * tanhf(cc);
                }
            }
        }
    }
    __syncthreads();

    if (h_f32) {
        #pragma unroll
        for (int i = 0; i < 2; i++) {
            int idx = i * 128 + tid;
            int row = idx >> 2, q = idx & 3;
            float4 v;
            v.x = s_h[row * 17 + q * 4 + 0];
            v.y = s_h[row * 17 + q * 4 + 1];
            v.z = s_h[row * 17 + q * 4 + 2];
            v.w = s_h[row * 17 + q * 4 + 3];
            *(float4*)(h_f32 + (size_t)(m0 + row) * LSTM + u0g + q * 4) = v;
        }
    }
    if (h_h16) {
        #pragma unroll
        for (int i = 0; i < 8; i++) {
            int idx = i * 128 + tid;             // [0,1024): 64 rows x 16 units
            int row = idx >> 4, u = idx & 15;
            h_h16[(size_t)(m0 + row) * K23PADH + 3 + u0g + u] =
                __float2half_rn(s_h[row * 17 + u]);
        }
    }
}

// ---------------------------------------------------------------------------
// Attention: writes w as half straight into X2/X3 at column 403.
// ---------------------------------------------------------------------------
__global__ void attention_kernel(const float* __restrict__ w_prev,
                                 const float* __restrict__ inputs,
                                 const float* __restrict__ h1n,
                                 const float* __restrict__ kappa,
                                 const float* __restrict__ W_attn,
                                 const float* __restrict__ b_attn,
                                 const float* __restrict__ AV,
                                 const int* __restrict__ lens,
                                 __half* __restrict__ X2,
                                 __half* __restrict__ X3)
{
    int b = blockIdx.x;
    __shared__ float s_in[ATTN_IN];
    __shared__ float s_par[3 * NATTN];
    __shared__ float s_alpha[NATTN], s_beta[NATTN], s_kap[NATTN];
    __shared__ float s_phi[CHARLEN];
    int t = threadIdx.x;

    for (int i = t; i < 73; i += 128)  s_in[i]      = w_prev[b * 73 + i];
    if (t < 3)                          s_in[73 + t] = inputs[b * 3 + t];
    for (int i = t; i < 400; i += 128) s_in[76 + i] = h1n[b * LSTM + i];
    __syncthreads();

    {
        int out = t >> 2, ln = t & 3;
        float acc = 0.f;
        if (out < 30) {
            const float* wr = W_attn + out * ATTN_IN;
            for (int k = ln; k < ATTN_IN; k += 4) acc = fmaf(s_in[k], wr[k], acc);
        }
        acc += __shfl_down_sync(0xffffffffu, acc, 2);
        acc += __shfl_down_sync(0xffffffffu, acc, 1);
        if (ln == 0 && out < 30) {
            float x = acc + b_attn[out];
            s_par[out] = (x > 20.f) ? x : log1pf(expf(x));
        }
    }
    __syncthreads();

    if (t < NATTN) {
        s_alpha[t] = s_par[t];
        s_beta[t]  = fmaxf(s_par[NATTN + t], 0.01f);
        s_kap[t]   = kappa[b * NATTN + t] + s_par[2 * NATTN + t] * 0.04f;
    }
    __syncthreads();

    int len = lens[b];
    if (t < CHARLEN) {
        float u = (float)t;
        float phi = 0.f;
        #pragma unroll
        for (int i = 0; i < NATTN; i++) {
            float d = s_kap[i] - u;
            phi += s_alpha[i] * expf(-d * d / s_beta[i]);
        }
        s_phi[t] = (t < len) ? phi : 0.f;
    }
    __syncthreads();

    for (int v = t; v < VOCAB; v += 128) {
        float acc = 0.f;
        const float* av = AV + (size_t)b * (CHARLEN * VOCAB) + v;
        #pragma unroll 8
        for (int c = 0; c < CHARLEN; c++) acc = fmaf(s_phi[c], av[c * VOCAB], acc);
        __half hv = __float2half_rn(acc);
        X2[(size_t)b * K23PADH + 403 + v] = hv;
        X3[(size_t)b * K23PADH + 403 + v] = hv;
    }
}

// ---------------------------------------------------------------------------
// Launch
// ---------------------------------------------------------------------------
extern "C" void kernel_launch(void* const* d_in, const int* in_sizes, int n_in,
                              void* d_out, int out_size)
{
    const float* inputs = (const float*)d_in[0];
    const float* h1     = (const float*)d_in[1];
    const float* c1     = (const float*)d_in[2];
    const float* h2     = (const float*)d_in[3];
    const float* c2     = (const float*)d_in[4];
    const float* h3     = (const float*)d_in[5];
    const float* c3     = (const float*)d_in[6];
    const float* kappa  = (const float*)d_in[7];
    const float* w_prev = (const float*)d_in[8];
    const float* AV     = (const float*)d_in[9];
    const int*   lens   = (const int*)  d_in[10];
    const float* W_ih1  = (const float*)d_in[11];
    const float* W_hh1  = (const float*)d_in[12];
    const float* b1     = (const float*)d_in[13];
    const float* W_attn = (const float*)d_in[14];
    const float* b_attn = (const float*)d_in[15];
    const float* W_ih2  = (const float*)d_in[16];
    const float* W_hh2  = (const float*)d_in[17];
    const float* b2     = (const float*)d_in[18];
    const float* W_ih3  = (const float*)d_in[19];
    const float* W_hh3  = (const float*)d_in[20];
    const float* b3     = (const float*)d_in[21];
    float* out = (float*)d_out;

    __half *Wt1, *Wt2, *Wt3, *X1, *X2, *X3;
    float *h1n;
    cudaGetSymbolAddress((void**)&Wt1,  g_Wt1);
    cudaGetSymbolAddress((void**)&Wt2,  g_Wt2);
    cudaGetSymbolAddress((void**)&Wt3,  g_Wt3);
    cudaGetSymbolAddress((void**)&X1,   g_X1);
    cudaGetSymbolAddress((void**)&X2,   g_X2);
    cudaGetSymbolAddress((void**)&X3,   g_X3);
    cudaGetSymbolAddress((void**)&h1n,  g_h1n);

    cudaFuncSetAttribute(gemm_lstm, cudaFuncAttributeMaxDynamicSharedMemorySize, SMEM_GEMM);

    pack_all<<<(PACK_TOTAL + 255) / 256, 256>>>(W_ih1, W_hh1, W_ih2, W_hh2, W_ih3, W_hh3,
                                                w_prev, inputs, h1, h2, h3,
                                                Wt1, Wt2, Wt3, X1, X2, X3);

    dim3 ggrid(NGATE / NTILE, BATCH / MTILE);   // (25, 64)

    // LSTM 1: h1n fp32 (for attention) + half into X2 cols [3,403)
    gemm_lstm<<<ggrid, 128, SMEM_GEMM>>>(X1, Wt1, b1, c1, h1n, X2, K1PADH, K1PADH / 64);

    // Attention -> w half into X2/X3 cols [403,476)
    attention_kernel<<<BATCH, 128>>>(w_prev, inputs, h1n, kappa, W_attn, b_attn,
                                     AV, lens, X2, X3);

    // LSTM 2: half into X3 cols [3,403)
    gemm_lstm<<<ggrid, 128, SMEM_GEMM>>>(X2, Wt2, b2, c2, nullptr, X3, K23PADH, K23PADH / 64);

    // LSTM 3: fp32 to out
    gemm_lstm<<<ggrid, 128, SMEM_GEMM>>>(X3, Wt3, b3, c3, out, nullptr, K23PADH, K23PADH / 64);
}

// round 14
// speedup vs baseline: 1.3536x; 1.0201x over previous
#include <cuda_runtime.h>
#include <cuda_fp16.h>
#include <math.h>
#include <stdint.h>

// ---------------------------------------------------------------------------
// Problem constants
// ---------------------------------------------------------------------------
#define BATCH   4096
#define LSTM    400
#define VOCAB   73
#define NATTN   10
#define CHARLEN 64
#define NGATE   1600
#define K1PADH  512
#define K23PADH 896
#define ATTN_IN 476
#define NTILE   64
#define MTILE   64
#define NBLK    25              // NGATE/NTILE
#define MBLK    64              // BATCH/MTILE

// mega-kernel block ranges
#define T_L1   (NBLK * MBLK)            // 1600
#define T_ATT  BATCH                    // 4096
#define B_ATT  T_L1
#define B_L2   (B_ATT + T_ATT)          // 5696
#define B_L3   (B_L2 + T_L1)            // 7296
#define B_END  (B_L3 + T_L1)            // 8896

// ---------------------------------------------------------------------------
// Scratch + dependency flags
// ---------------------------------------------------------------------------
__device__ __half g_Wt1[NGATE * K1PADH];
__device__ __half g_Wt2[NGATE * K23PADH];
__device__ __half g_Wt3[NGATE * K23PADH];
__device__ __half g_X1 [BATCH * K1PADH];
__device__ __half g_X2 [BATCH * K23PADH];
__device__ __half g_X3 [BATCH * K23PADH];
__device__ float  g_h1n[BATCH * LSTM];
__device__ int    g_flags[192];   // [0,64)=done1, [64,128)=doneA, [128,192)=done2

#define CPASYNC16(dst, src) \
    asm volatile("cp.async.cg.shared.global [%0], [%1], 16;" :: "r"(dst), "l"(src) : "memory")

__device__ __forceinline__ uint32_t smem_to_u32(const void* p) {
    uint32_t a;
    asm("{ .reg .u64 t; cvta.to.shared.u64 t, %1; cvt.u32.u64 %0, t; }" : "=r"(a) : "l"(p));
    return a;
}

__device__ __forceinline__ uint32_t swz(uint32_t off) {
    return off ^ ((off >> 3) & 0x70);
}

__device__ __forceinline__ void mma_f16(float* d, const uint32_t* a, const uint32_t* b) {
    asm volatile(
        "mma.sync.aligned.m16n8k16.row.col.f32.f16.f16.f32 "
        "{%0,%1,%2,%3}, {%4,%5,%6,%7}, {%8,%9}, {%0,%1,%2,%3};"
        : "+f"(d[0]), "+f"(d[1]), "+f"(d[2]), "+f"(d[3])
        : "r"(a[0]), "r"(a[1]), "r"(a[2]), "r"(a[3]), "r"(b[0]), "r"(b[1]));
}

__device__ __forceinline__ void ldsm_x4(uint32_t& r0, uint32_t& r1, uint32_t& r2,
                                        uint32_t& r3, uint32_t addr) {
    asm volatile("ldmatrix.sync.aligned.m8n8.x4.shared.b16 {%0,%1,%2,%3}, [%4];"
                 : "=r"(r0), "=r"(r1), "=r"(r2), "=r"(r3) : "r"(addr));
}

__device__ __forceinline__ void spin_ge(volatile int* p, int target) {
    while (*p < target) __nanosleep(128);
}

// ---------------------------------------------------------------------------
// ONE merged pack kernel: flags | W1 | W2 | W3 | X1 | X23-static
// ---------------------------------------------------------------------------
#define R_W1  (NGATE * K1PADH)
#define R_W2  (R_W1 + NGATE * K23PADH)
#define R_W3  (R_W2 + NGATE * K23PADH)
#define R_X1  (R_W3 + BATCH * K1PADH)
#define XSCOL 423
#define PACK_TOTAL (R_X1 + BATCH * XSCOL)

__global__ void pack_all(const float* __restrict__ W_ih1, const float* __restrict__ W_hh1,
                         const float* __restrict__ W_ih2, const float* __restrict__ W_hh2,
                         const float* __restrict__ W_ih3, const float* __restrict__ W_hh3,
                         const float* __restrict__ w_prev, const float* __restrict__ inputs,
                         const float* __restrict__ h1, const float* __restrict__ h2,
                         const float* __restrict__ h3,
                         __half* __restrict__ Wt1, __half* __restrict__ Wt2,
                         __half* __restrict__ Wt3, __half* __restrict__ X1,
                         __half* __restrict__ X2, __half* __restrict__ X3)
{
    int idx = blockIdx.x * blockDim.x + threadIdx.x;
    if (idx < 192) g_flags[idx] = 0;
    if (idx >= PACK_TOTAL) return;
    if (idx < R_W1) {
        int np = idx / K1PADH, k = idx - np * K1PADH;
        int n = (np & 3) * LSTM + (np >> 2);
        float v = 0.f;
        if (k < 76)            v = W_ih1[n * 76 + k];
        else if (k < 476)      v = W_hh1[n * LSTM + (k - 76)];
        Wt1[idx] = __float2half_rn(v);
    } else if (idx < R_W2) {
        int r = idx - R_W1;
        int np = r / K23PADH, k = r - np * K23PADH;
        int n = (np & 3) * LSTM + (np >> 2);
        float v = 0.f;
        if (k < 476)           v = W_ih2[n * 476 + k];
        else if (k < 876)      v = W_hh2[n * LSTM + (k - 476)];
        Wt2[r] = __float2half_rn(v);
    } else if (idx < R_W3) {
        int r = idx - R_W2;
        int np = r / K23PADH, k = r - np * K23PADH;
        int n = (np & 3) * LSTM + (np >> 2);
        float v = 0.f;
        if (k < 476)           v = W_ih3[n * 476 + k];
        else if (k < 876)      v = W_hh3[n * LSTM + (k - 476)];
        Wt3[r] = __float2half_rn(v);
    } else if (idx < R_X1) {
        int r = idx - R_W3;
        int b = r >> 9, c = r & 511;
        float v;
        if      (c < 73)  v = w_prev[b * 73 + c];
        else if (c < 76)  v = inputs[b * 3 + (c - 73)];
        else if (c < 476) v = h1[b * LSTM + (c - 76)];
        else              v = 0.f;
        X1[r] = __float2half_rn(v);
    } else {
        int r = idx - R_X1;
        int b = r / XSCOL, cp = r - b * XSCOL;
        int c = (cp < 3) ? cp : (cp + 473);
        __half v2, v3;
        if (c < 3) {
            __half v = __float2half_rn(inputs[b * 3 + c]);
            v2 = v; v3 = v;
        } else if (c < 876) {
            v2 = __float2half_rn(h2[b * LSTM + (c - 476)]);
            v3 = __float2half_rn(h3[b * LSTM + (c - 476)]);
        } else {
            v2 = __float2half_rn(0.f); v3 = v2;
        }
        size_t o = (size_t)b * K23PADH + c;
        X2[o] = v2; X3[o] = v3;
    }
}

// ---------------------------------------------------------------------------
// GEMM tile (r13-proven): CTA 64x64, 4 warps (2Mx2N), warp 32x32, BK=64,
// SW128-swizzled smem, cp.async staging, ldmatrix fragments, fused LSTM.
// ---------------------------------------------------------------------------
#define A_BYTES  (MTILE * 128)               // 8192
#define B_BYTES  (NTILE * 128)               // 8192
#define STAGE_BYTES (A_BYTES + B_BYTES)      // 16384
#define SMEM_GEMM (2 * STAGE_BYTES)          // 32768

__device__ __forceinline__ void gemm_tile(
    char* smem, const __half* __restrict__ A, const __half* __restrict__ Bw,
    const float* __restrict__ bias, const float* __restrict__ c_in,
    float* __restrict__ h_f32, __half* __restrict__ h_h16,
    int KPAD, int NC, int n0, int m0)
{
    float* smemf = (float*)smem;
    const uint32_t sb = smem_to_u32(smem);
    const int tid = threadIdx.x, wid = tid >> 5, lane = tid & 31;
    const int warp_m = wid & 1, warp_n = wid >> 1;

    const __half* Ag = A  + (size_t)m0 * KPAD;
    const __half* Bg = Bw + (size_t)n0 * KPAD;

    float acc[2][4][4];
    #pragma unroll
    for (int mt = 0; mt < 2; mt++)
        #pragma unroll
        for (int nt = 0; nt < 4; nt++)
            #pragma unroll
            for (int q = 0; q < 4; q++) acc[mt][nt][q] = 0.f;

    const int lane8 = lane & 7, mat = lane >> 3;
    uint32_t abase[2], bbase[2];
    #pragma unroll
    for (int mt = 0; mt < 2; mt++) {
        int arow = warp_m * 32 + mt * 16 + (mat & 1) * 8 + lane8;
        abase[mt] = (uint32_t)(arow * 128 + (mat >> 1) * 16);
    }
    #pragma unroll
    for (int p = 0; p < 2; p++) {
        int brow = warp_n * 32 + p * 16 + (mat >> 1) * 8 + lane8;
        bbase[p] = (uint32_t)(brow * 128 + (mat & 1) * 16);
    }

    auto issue_chunk = [&](int c, int stage) {
        uint32_t abuf = sb + stage * STAGE_BYTES;
        uint32_t bbuf = abuf + A_BYTES;
        int k0 = c * 64;
        #pragma unroll
        for (int i = 0; i < 4; i++) {
            int o = i * 128 + tid;
            int row = o >> 3, seg = o & 7;
            CPASYNC16(abuf + swz(row * 128 + seg * 16),
                      Ag + (size_t)row * KPAD + k0 + seg * 8);
        }
        #pragma unroll
        for (int i = 0; i < 4; i++) {
            int o = i * 128 + tid;
            int row = o >> 3, seg = o & 7;
            CPASYNC16(bbuf + swz(row * 128 + seg * 16),
                      Bg + (size_t)row * KPAD + k0 + seg * 8);
        }
        asm volatile("cp.async.commit_group;" ::: "memory");
    };

    issue_chunk(0, 0);

    #pragma unroll 1
    for (int c = 0; c < NC; ++c) {
        asm volatile("cp.async.wait_group 0;" ::: "memory");
        __syncthreads();
        if (c + 1 < NC) issue_chunk(c + 1, (c + 1) & 1);

        const uint32_t abuf = sb + (c & 1) * STAGE_BYTES;
        const uint32_t bbuf = abuf + A_BYTES;
        #pragma unroll
        for (int ks = 0; ks < 4; ks++) {
            uint32_t kb = ks * 32;
            uint32_t a[2][4], b[4][2];
            ldsm_x4(a[0][0], a[0][1], a[0][2], a[0][3], abuf + swz(abase[0] + kb));
            ldsm_x4(a[1][0], a[1][1], a[1][2], a[1][3], abuf + swz(abase[1] + kb));
            ldsm_x4(b[0][0], b[0][1], b[1][0], b[1][1], bbuf + swz(bbase[0] + kb));
            ldsm_x4(b[2][0], b[2][1], b[3][0], b[3][1], bbuf + swz(bbase[1] + kb));
            #pragma unroll
            for (int mt = 0; mt < 2; mt++)
                #pragma unroll
                for (int nt = 0; nt < 4; nt++)
                    mma_f16(acc[mt][nt], a[mt], b[nt]);
        }
    }
    __syncthreads();

    float* s_c    = smemf;
    float* s_h    = smemf + 64 * 17;
    float* s_bias = smemf + 2 * 64 * 17;

    const int u0g = n0 >> 2;
    if (tid < NTILE) {
        int jg = n0 + tid;
        s_bias[tid] = bias[(jg & 3) * LSTM + (jg >> 2)];
    }
    #pragma unroll
    for (int i = 0; i < 2; i++) {
        int idx = i * 128 + tid;
        int row = idx >> 2, q = idx & 3;
        float4 v = *(const float4*)(c_in + (size_t)(m0 + row) * LSTM + u0g + q * 4);
        s_c[row * 17 + q * 4 + 0] = v.x;
        s_c[row * 17 + q * 4 + 1] = v.y;
        s_c[row * 17 + q * 4 + 2] = v.z;
        s_c[row * 17 + q * 4 + 3] = v.w;
    }
    __syncthreads();

    const int gid = lane >> 2, tig = lane & 3;
    #pragma unroll
    for (int mt = 0; mt < 2; mt++) {
        #pragma unroll
        for (int nt = 0; nt < 4; nt++) {
            float p0 = __shfl_xor_sync(0xffffffffu, acc[mt][nt][0], 1);
            float p1 = __shfl_xor_sync(0xffffffffu, acc[mt][nt][1], 1);
            float p2 = __shfl_xor_sync(0xffffffffu, acc[mt][nt][2], 1);
            float p3 = __shfl_xor_sync(0xffffffffu, acc[mt][nt][3], 1);
            if (!(lane & 1)) {
                int jb = warp_n * 32 + nt * 8 + tig * 2;
                int u  = jb >> 2;
                float bi = s_bias[jb], bf = s_bias[jb + 1];
                float bg = s_bias[jb + 2], bo = s_bias[jb + 3];
                int r0 = warp_m * 32 + mt * 16 + gid;
                #pragma unroll
                for (int hh = 0; hh < 2; hh++) {
                    int r = r0 + hh * 8;
                    float vi = (hh ? acc[mt][nt][2] : acc[mt][nt][0]) + bi;
                    float vf = (hh ? acc[mt][nt][3] : acc[mt][nt][1]) + bf;
                    float vg = (hh ? p2 : p0) + bg;
                    float vo = (hh ? p3 : p1) + bo;
                    float ii = 1.f / (1.f + expf(-vi));
                    float ff = 1.f / (1.f + expf(-vf));
                    float oo = 1.f / (1.f + expf(-vo));
                    float gg = tanhf(vg);
                    float cc = ff * s_c[r * 17 + u] + ii * gg;
                    s_h[r * 17 + u] = oo * tanhf(cc);
                }
            }
        }
    }
    __syncthreads();

    if (h_f32) {
        #pragma unroll
        for (int i = 0; i < 2; i++) {
            int idx = i * 128 + tid;
            int row = idx >> 2, q = idx & 3;
            float4 v;
            v.x = s_h[row * 17 + q * 4 + 0];
            v.y = s_h[row * 17 + q * 4 + 1];
            v.z = s_h[row * 17 + q * 4 + 2];
            v.w = s_h[row * 17 + q * 4 + 3];
            *(float4*)(h_f32 + (size_t)(m0 + row) * LSTM + u0g + q * 4) = v;
        }
    }
    if (h_h16) {
        #pragma unroll
        for (int i = 0; i < 8; i++) {
            int idx = i * 128 + tid;
            int row = idx >> 4, u = idx & 15;
            h_h16[(size_t)(m0 + row) * K23PADH + 3 + u0g + u] =
                __float2half_rn(s_h[row * 17 + u]);
        }
    }
}

// ---------------------------------------------------------------------------
// Attention body (one batch row per block), writes w half into X2/X3 col 403.
// ---------------------------------------------------------------------------
__device__ __forceinline__ void attention_body(
    char* smem, int b,
    const float* __restrict__ w_prev, const float* __restrict__ inputs,
    const float* __restrict__ h1n, const float* __restrict__ kappa,
    const float* __restrict__ W_attn, const float* __restrict__ b_attn,
    const float* __restrict__ AV, const int* __restrict__ lens,
    __half* __restrict__ X2, __half* __restrict__ X3)
{
    float* s_in    = (float*)smem;                 // [476]
    float* s_par   = s_in + ATTN_IN;               // [30]
    float* s_alpha = s_par + 3 * NATTN;            // [10]
    float* s_beta  = s_alpha + NATTN;              // [10]
    float* s_kap   = s_beta + NATTN;               // [10]
    float* s_phi   = s_kap + NATTN;                // [64]
    int t = threadIdx.x;

    for (int i = t; i < 73; i += 128)  s_in[i]      = w_prev[b * 73 + i];
    if (t < 3)                          s_in[73 + t] = inputs[b * 3 + t];
    for (int i = t; i < 400; i += 128) s_in[76 + i] = h1n[b * LSTM + i];
    __syncthreads();

    {
        int out = t >> 2, ln = t & 3;
        float acc = 0.f;
        if (out < 30) {
            const float* wr = W_attn + out * ATTN_IN;
            for (int k = ln; k < ATTN_IN; k += 4) acc = fmaf(s_in[k], wr[k], acc);
        }
        acc += __shfl_down_sync(0xffffffffu, acc, 2);
        acc += __shfl_down_sync(0xffffffffu, acc, 1);
        if (ln == 0 && out < 30) {
            float x = acc + b_attn[out];
            s_par[out] = (x > 20.f) ? x : log1pf(expf(x));
        }
    }
    __syncthreads();

    if (t < NATTN) {
        s_alpha[t] = s_par[t];
        s_beta[t]  = fmaxf(s_par[NATTN + t], 0.01f);
        s_kap[t]   = kappa[b * NATTN + t] + s_par[2 * NATTN + t] * 0.04f;
    }
    __syncthreads();

    int len = lens[b];
    if (t < CHARLEN) {
        float u = (float)t;
        float phi = 0.f;
        #pragma unroll
        for (int i = 0; i < NATTN; i++) {
            float d = s_kap[i] - u;
            phi += s_alpha[i] * expf(-d * d / s_beta[i]);
        }
        s_phi[t] = (t < len) ? phi : 0.f;
    }
    __syncthreads();

    for (int v = t; v < VOCAB; v += 128) {
        float acc = 0.f;
        const float* av = AV + (size_t)b * (CHARLEN * VOCAB) + v;
        #pragma unroll 8
        for (int c = 0; c < CHARLEN; c++) acc = fmaf(s_phi[c], av[c * VOCAB], acc);
        __half hv = __float2half_rn(acc);
        X2[(size_t)b * K23PADH + 403 + v] = hv;
        X3[(size_t)b * K23PADH + 403 + v] = hv;
    }
}

// ---------------------------------------------------------------------------
// MEGA kernel: [L1 tiles | attention | L2 tiles | L3 tiles], in-order
// dispatch + per-mblock dependency counters. Tiles ordered m-major so
// early m-blocks complete first.
// ---------------------------------------------------------------------------
__global__ __launch_bounds__(128, 7)
void mega(const __half* __restrict__ X1, const __half* __restrict__ X2,
          const __half* __restrict__ X3,
          const __half* __restrict__ Wt1, const __half* __restrict__ Wt2,
          const __half* __restrict__ Wt3,
          const float* __restrict__ b1, const float* __restrict__ b2,
          const float* __restrict__ b3,
          const float* __restrict__ c1, const float* __restrict__ c2,
          const float* __restrict__ c3,
          float* __restrict__ h1n, float* __restrict__ out,
          const float* __restrict__ w_prev, const float* __restrict__ inputs,
          const float* __restrict__ kappa, const float* __restrict__ W_attn,
          const float* __restrict__ b_attn, const float* __restrict__ AV,
          const int* __restrict__ lens)
{
    extern __shared__ char smem[];
    const int bid = blockIdx.x;
    const int tid = threadIdx.x;
    volatile int* done1 = (volatile int*)g_flags;
    volatile int* doneA = (volatile int*)(g_flags + 64);
    volatile int* done2 = (volatile int*)(g_flags + 128);

    if (bid < T_L1) {
        // ---- layer 1 ----
        int m_idx = bid / NBLK, n_idx = bid - m_idx * NBLK;
        gemm_tile(smem, X1, Wt1, b1, c1, h1n, (__half*)X2,
                  K1PADH, K1PADH / 64, n_idx * NTILE, m_idx * MTILE);
        __syncthreads();
        __threadfence();
        if (tid == 0) atomicAdd(&g_flags[m_idx], 1);
    } else if (bid < B_L2) {
        // ---- attention (one batch row) ----
        int b = bid - B_ATT;
        if (tid == 0) {
            spin_ge(&done1[b >> 6], NBLK);
            __threadfence();            // CCTL.IVALL: fresh h1n through L1
        }
        __syncthreads();
        attention_body(smem, b, w_prev, inputs, h1n, kappa, W_attn, b_attn,
                       AV, lens, (__half*)X2, (__half*)X3);
        __syncthreads();
        __threadfence();
        if (tid == 0) atomicAdd(&g_flags[64 + (b >> 6)], 1);
    } else if (bid < B_L3) {
        // ---- layer 2 ----
        int t2 = bid - B_L2;
        int m_idx = t2 / NBLK, n_idx = t2 - m_idx * NBLK;
        if (tid == 0) {
            spin_ge(&done1[m_idx], NBLK);
            spin_ge(&doneA[m_idx], MTILE);
            __threadfence();
        }
        __syncthreads();
        gemm_tile(smem, X2, Wt2, b2, c2, nullptr, (__half*)X3,
                  K23PADH, K23PADH / 64, n_idx * NTILE, m_idx * MTILE);
        __syncthreads();
        __threadfence();
        if (tid == 0) atomicAdd(&g_flags[128 + m_idx], 1);
    } else {
        // ---- layer 3 ----
        int t3 = bid - B_L3;
        int m_idx = t3 / NBLK, n_idx = t3 - m_idx * NBLK;
        if (tid == 0) {
            spin_ge(&done2[m_idx], NBLK);
            spin_ge(&doneA[m_idx], MTILE);
            __threadfence();
        }
        __syncthreads();
        gemm_tile(smem, X3, Wt3, b3, c3, out, nullptr,
                  K23PADH, K23PADH / 64, n_idx * NTILE, m_idx * MTILE);
    }
}

// ---------------------------------------------------------------------------
// Launch
// ---------------------------------------------------------------------------
extern "C" void kernel_launch(void* const* d_in, const int* in_sizes, int n_in,
                              void* d_out, int out_size)
{
    const float* inputs = (const float*)d_in[0];
    const float* h1     = (const float*)d_in[1];
    const float* c1     = (const float*)d_in[2];
    const float* h2     = (const float*)d_in[3];
    const float* c2     = (const float*)d_in[4];
    const float* h3     = (const float*)d_in[5];
    const float* c3     = (const float*)d_in[6];
    const float* kappa  = (const float*)d_in[7];
    const float* w_prev = (const float*)d_in[8];
    const float* AV     = (const float*)d_in[9];
    const int*   lens   = (const int*)  d_in[10];
    const float* W_ih1  = (const float*)d_in[11];
    const float* W_hh1  = (const float*)d_in[12];
    const float* b1     = (const float*)d_in[13];
    const float* W_attn = (const float*)d_in[14];
    const float* b_attn = (const float*)d_in[15];
    const float* W_ih2  = (const float*)d_in[16];
    const float* W_hh2  = (const float*)d_in[17];
    const float* b2     = (const float*)d_in[18];
    const float* W_ih3  = (const float*)d_in[19];
    const float* W_hh3  = (const float*)d_in[20];
    const float* b3     = (const float*)d_in[21];
    float* out = (float*)d_out;

    __half *Wt1, *Wt2, *Wt3, *X1, *X2, *X3;
    float *h1n;
    cudaGetSymbolAddress((void**)&Wt1,  g_Wt1);
    cudaGetSymbolAddress((void**)&Wt2,  g_Wt2);
    cudaGetSymbolAddress((void**)&Wt3,  g_Wt3);
    cudaGetSymbolAddress((void**)&X1,   g_X1);
    cudaGetSymbolAddress((void**)&X2,   g_X2);
    cudaGetSymbolAddress((void**)&X3,   g_X3);
    cudaGetSymbolAddress((void**)&h1n,  g_h1n);

    cudaFuncSetAttribute(mega, cudaFuncAttributeMaxDynamicSharedMemorySize, SMEM_GEMM);

    pack_all<<<(PACK_TOTAL + 255) / 256, 256>>>(W_ih1, W_hh1, W_ih2, W_hh2, W_ih3, W_hh3,
                                                w_prev, inputs, h1, h2, h3,
                                                Wt1, Wt2, Wt3, X1, X2, X3);

    mega<<<B_END, 128, SMEM_GEMM>>>(X1, X2, X3, Wt1, Wt2, Wt3,
                                    b1, b2, b3, c1, c2, c3,
                                    h1n, out,
                                    w_prev, inputs, kappa, W_attn, b_attn,
                                    AV, lens);
}